// round 12
// baseline (speedup 1.0000x reference)
#include <cuda_runtime.h>
#include <math.h>

#define PN 22
#define DN 3
#define HN 64
#define LN 5
#define NWARP 22
#define NTHREADS 704
#define CRC 3.0f       /* 15.0 / 5 layers */
#define LOG2M 7.0f

typedef unsigned long long ull;

/* ---- shared memory layout (floats) ---- */
constexpr int OFF_EW2  = 0;        /* 64*64  col-major + k-swizzle */
constexpr int OFF_CW1  = 4096;     /* 64*64  col-major + k-swizzle */
constexpr int OFF_NW1  = 8192;     /* 128*64 row-major */
constexpr int OFF_NW2  = 16384;    /* 64*64  row-major */
constexpr int OFF_EW1R = 20480;    /* ew1 rows 128,129 -> 128 floats */
constexpr int OFF_EB1  = 20608;
constexpr int OFF_EB2  = 20672;
constexpr int OFF_NB1  = 20736;
constexpr int OFF_NB2  = 20800;
constexpr int OFF_CB1  = 20864;
constexpr int OFF_CW2  = 20928;
constexpr int OFF_AW   = 20992;
constexpr int OFF_AB   = 21056;    /* +pad */
constexpr int OFF_H    = 21060;    /* 2 * 22*64 */
constexpr int OFF_HR   = 23876;
constexpr int OFF_HC   = 26692;
constexpr int OFF_EA   = 29508;    /* 2 * 484 */
constexpr int OFF_CRD  = 30476;    /* 2 * 68 */
constexpr int OFF_CR0  = 30612;
constexpr int OFF_VEL  = 30748;
constexpr int OFF_MEAN = 30884;    /* 8 */
constexpr int OFF_AGG  = 30892;    /* 22 warps * 2 mols * 64 = 2816 */
constexpr int OFF_WB   = 33708;    /* 22 warps * 12 edges * 64 = 16896 floats */
constexpr int SMEM_FLOATS = 50604; /* 202,416 bytes */

__device__ __forceinline__ float sigmf_(float v) {
    return __fdividef(1.f, 1.f + __expf(-v));
}
__device__ __forceinline__ float siluf(float v) { return v * sigmf_(v); }
__device__ __forceinline__ float tanhfast(float v) {
    const float e2 = __expf(2.f * v);
    return 1.f - __fdividef(2.f, e2 + 1.f);
}

__device__ __forceinline__ void ffma2(ull& d, ull a, ull b) {
    asm("fma.rn.f32x2 %0, %1, %2, %0;" : "+l"(d) : "l"(a), "l"(b));
}
__device__ __forceinline__ ull pack2(float x, float y) {
    ull r; asm("mov.b64 %0, {%1, %2};" : "=l"(r) : "f"(x), "f"(y)); return r;
}
__device__ __forceinline__ void unpack2(ull v, float& x, float& y) {
    asm("mov.b64 {%0, %1}, %2;" : "=f"(x), "=f"(y) : "l"(v));
}

/* k-paired 12-edge GEMV (6 per half-warp), 4 cols/lane, zero packs.
   WmT: 64x64 col-major, swizzled: W[k][c] stored at WmT[c*64 + (k ^ swz(c))],
   swz(c) = ((c>>2)&7)<<2.  Lane handling cols c4..c4+3 reads weights at
   kx = k ^ xorv (xorv == swz(c4..c4+3), constant per lane) -> after the
   double-XOR the register pair is {W[k][c],W[k+1][c]}.  Activations are
   stored plain and read at plain k (broadcast across the half-warp).
   u[e][q] accumulates col c4+q over (lo=even k, hi=odd k). */
__device__ __forceinline__ void gemvKP6(const float* __restrict__ WmT,
                                        const float* __restrict__ actf,
                                        const int c4, const int xorv, ull u[6][4])
{
#pragma unroll 4
    for (int k = 0; k < HN; k += 4) {
        const int kx = k ^ xorv;
        const ulonglong2 w0 = *(const ulonglong2*)&WmT[(c4 + 0) * HN + kx];
        const ulonglong2 w1 = *(const ulonglong2*)&WmT[(c4 + 1) * HN + kx];
        const ulonglong2 w2 = *(const ulonglong2*)&WmT[(c4 + 2) * HN + kx];
        const ulonglong2 w3 = *(const ulonglong2*)&WmT[(c4 + 3) * HN + kx];
#pragma unroll
        for (int e = 0; e < 6; ++e) {
            const ulonglong2 a = *(const ulonglong2*)&actf[e * HN + k];
            ffma2(u[e][0], a.x, w0.x); ffma2(u[e][0], a.y, w0.y);
            ffma2(u[e][1], a.x, w1.x); ffma2(u[e][1], a.y, w1.y);
            ffma2(u[e][2], a.x, w2.x); ffma2(u[e][2], a.y, w2.y);
            ffma2(u[e][3], a.x, w3.x); ffma2(u[e][3], a.y, w3.y);
        }
    }
}

__global__ __launch_bounds__(NTHREADS, 1)
void egnn_kernel(const float* __restrict__ t, const float* __restrict__ x,
                 const float* __restrict__ embW, const float* __restrict__ embb,
                 const float* __restrict__ ew1, const float* __restrict__ eb1,
                 const float* __restrict__ ew2, const float* __restrict__ eb2,
                 const float* __restrict__ nw1, const float* __restrict__ nb1,
                 const float* __restrict__ nw2, const float* __restrict__ nb2,
                 const float* __restrict__ cw1, const float* __restrict__ cb1,
                 const float* __restrict__ cw2, const float* __restrict__ aw,
                 const float* __restrict__ ab, float* __restrict__ out)
{
    extern __shared__ float sm[];
    const int tid = threadIdx.x;
    const int b0 = blockIdx.x * 2;       /* molecules b0, b0+1 */
    const int w = tid >> 5;
    const int lane = tid & 31;
    const int hw = lane >> 4;            /* half-warp: edge subset */
    const int c4 = (lane & 15) * 4;      /* 4 output cols per lane */
    const int xorv = (lane & 7) << 2;    /* == swz(c4) */
    const int i = w;                     /* node owned by this warp (both mols) */

    /* ---- init: coords, h, edge_attr ---- */
    for (int idx = tid; idx < 2 * PN * DN; idx += NTHREADS) {
        const int m = idx / 66, rem = idx - m * 66;
        const float c = x[(b0 + m) * 66 + rem];
        sm[OFF_CRD + m * 68 + rem] = c;
        sm[OFF_CR0 + m * 68 + rem] = c;
    }
    const float tA = t[b0], tB = t[b0 + 1];
    for (int idx = tid; idx < 2 * PN * HN; idx += NTHREADS) {
        const int m = idx / 1408, q = idx - m * 1408;
        const int ii = q >> 6, o = q & 63;
        const float tb = m ? tB : tA;
        sm[OFF_H + m * 1408 + q] = embW[ii * HN + o] + tb * embW[22 * HN + o]
                                 + LOG2M * embW[23 * HN + o] + embb[o];
    }
    __syncthreads();
    for (int idx = tid; idx < 2 * PN * PN; idx += NTHREADS) {
        const int m = idx / 484, q = idx - m * 484;
        const int ii = q / PN, jj = q - ii * PN;
        const float dx = sm[OFF_CRD + m*68 + ii*3+0] - sm[OFF_CRD + m*68 + jj*3+0];
        const float dy = sm[OFF_CRD + m*68 + ii*3+1] - sm[OFF_CRD + m*68 + jj*3+1];
        const float dz = sm[OFF_CRD + m*68 + ii*3+2] - sm[OFF_CRD + m*68 + jj*3+2];
        sm[OFF_EA + m*484 + q] = dx*dx + dy*dy + dz*dz;
    }
    /* ordered before use by the weight-staging barrier below */

    float* const actm = sm + OFF_WB + w * 768 + hw * 384;  /* my half: 6x64 */
    float* const wbf  = sm + OFF_WB + w * 768;             /* warp scratch (phase 3) */
    float* const aggp = sm + OFF_AGG + w * 128;            /* [mol][64], dedicated */

    for (int l = 0; l < LN; ++l) {
        const float* s1 = ew1 + l * 8320;    /* rows 0..127 read straight from L2 */
        /* ---- stage this layer's weights (ew2/cw1 transposed + swizzled) ---- */
        {
            const float* s2 = ew2 + l * 4096;
            for (int q0 = tid; q0 < 4096; q0 += NTHREADS) {
                const int k = q0 >> 6, c = q0 & 63;
                sm[OFF_EW2 + c * 64 + (k ^ (((c >> 2) & 7) << 2))] = s2[q0];
            }
            const float* s5 = cw1 + l * 4096;
            for (int q0 = tid; q0 < 4096; q0 += NTHREADS) {
                const int k = q0 >> 6, c = q0 & 63;
                sm[OFF_CW1 + c * 64 + (k ^ (((c >> 2) & 7) << 2))] = s5[q0];
            }
            const float* s3 = nw1 + l * 8192;
            for (int q0 = tid; q0 < 8192; q0 += NTHREADS) sm[OFF_NW1 + q0] = s3[q0];
            const float* s4 = nw2 + l * 4096;
            for (int q0 = tid; q0 < 4096; q0 += NTHREADS) sm[OFF_NW2 + q0] = s4[q0];
            if (tid < 128) sm[OFF_EW1R + tid] = s1[128 * 64 + tid];
            if (tid >= 128 && tid < 192) {
                const int o = tid - 128;
                sm[OFF_EB1 + o] = eb1[l * 64 + o];
                sm[OFF_EB2 + o] = eb2[l * 64 + o];
                sm[OFF_NB1 + o] = nb1[l * 64 + o];
                sm[OFF_NB2 + o] = nb2[l * 64 + o];
                sm[OFF_CB1 + o] = cb1[l * 64 + o];
                sm[OFF_CW2 + o] = cw2[l * 64 + o];
                sm[OFF_AW + o]  = aw[l * 64 + o];
            }
            if (tid == 0) sm[OFF_AB] = ab[l];
        }
        __syncthreads();

        /* ---- phase 1: Hr/Hc for node i, both molecules (ew1 via L2) ---- */
        {
            ull r2a = 0ull, c2a = 0ull, r2b = 0ull, c2b = 0ull;
            const float* hA = &sm[OFF_H + i * 64];
            const float* hB = &sm[OFF_H + 1408 + i * 64];
#pragma unroll 4
            for (int k = 0; k < HN; ++k) {
                const ull wr = *(const ull*)&s1[k * 64 + 2 * lane];
                const ull wc = *(const ull*)&s1[(64 + k) * 64 + 2 * lane];
                const float aA = hA[k]; const ull apA = pack2(aA, aA);
                const float aB = hB[k]; const ull apB = pack2(aB, aB);
                ffma2(r2a, apA, wr); ffma2(c2a, apA, wc);
                ffma2(r2b, apB, wr); ffma2(c2b, apB, wc);
            }
            *(ull*)&sm[OFF_HR + i * 64 + 2 * lane] = r2a;
            *(ull*)&sm[OFF_HC + i * 64 + 2 * lane] = c2a;
            *(ull*)&sm[OFF_HR + 1408 + i * 64 + 2 * lane] = r2b;
            *(ull*)&sm[OFF_HC + 1408 + i * 64 + 2 * lane] = c2b;
        }
        __syncthreads();

        /* ---- phase 2: 48-slot edge stream (2 mols x 21 + 6 pad),
                12 edges per pass (6 per half-warp), 4 passes ---- */
        float dcA0 = 0.f, dcA1 = 0.f, dcA2 = 0.f;
        float dcB0 = 0.f, dcB1 = 0.f, dcB2 = 0.f;
        float agA0 = 0.f, agA1 = 0.f, agA2 = 0.f, agA3 = 0.f;
        float agB0 = 0.f, agB1 = 0.f, agB2 = 0.f, agB3 = 0.f;

#pragma unroll 1
        for (int p = 0; p < 4; ++p) {
            /* setup: t1 = silu(e_in @ ew1 + eb1) -> actm (plain floats) */
            {
                const float4 w128 = *(const float4*)&sm[OFF_EW1R + c4];
                const float4 w129 = *(const float4*)&sm[OFF_EW1R + 64 + c4];
                const float4 b1   = *(const float4*)&sm[OFF_EB1 + c4];
#pragma unroll
                for (int e = 0; e < 6; ++e) {
                    const int eg  = p * 12 + hw * 6 + e;
                    const int mol = (eg >= 21) ? 1 : 0;
                    const int r   = eg - mol * 21;
                    const int pad = (r >= PN - 1);
                    int j = (r < i) ? r : r + 1;
                    if (pad) j = i;
                    const int mo68 = mol * 68, mo14 = mol * 1408, mo484 = mol * 484;
                    const float dx = sm[OFF_CRD + mo68 + i*3+0] - sm[OFF_CRD + mo68 + j*3+0];
                    const float dy = sm[OFF_CRD + mo68 + i*3+1] - sm[OFF_CRD + mo68 + j*3+1];
                    const float dz = sm[OFF_CRD + mo68 + i*3+2] - sm[OFF_CRD + mo68 + j*3+2];
                    const float radial = dx*dx + dy*dy + dz*dz;
                    const float eav = sm[OFF_EA + mo484 + i * PN + j];
                    const float4 hr = *(const float4*)&sm[OFF_HR + mo14 + i * 64 + c4];
                    const float4 hc = *(const float4*)&sm[OFF_HC + mo14 + j * 64 + c4];
                    float4 o;
                    o.x = siluf(hr.x + hc.x + b1.x + radial * w128.x + eav * w129.x);
                    o.y = siluf(hr.y + hc.y + b1.y + radial * w128.y + eav * w129.y);
                    o.z = siluf(hr.z + hc.z + b1.z + radial * w128.z + eav * w129.z);
                    o.w = siluf(hr.w + hc.w + b1.w + radial * w128.w + eav * w129.w);
                    *(float4*)&actm[e * HN + c4] = o;
                }
            }
            __syncwarp();

            /* GEMV2: m = silu(t1 @ ew2 + eb2) (k-paired, bias at epilogue) */
            ull u[6][4];
#pragma unroll
            for (int e = 0; e < 6; ++e) {
                u[e][0] = 0ull; u[e][1] = 0ull; u[e][2] = 0ull; u[e][3] = 0ull;
            }
            gemvKP6(&sm[OFF_EW2], actm, c4, xorv, u);

            const float4 b2  = *(const float4*)&sm[OFF_EB2 + c4];
            const float4 aw4 = *(const float4*)&sm[OFF_AW + c4];
            const float abv  = sm[OFF_AB];
            float mv[6][4], part[6];
#pragma unroll
            for (int e = 0; e < 6; ++e) {
                float l0, h0, l1, h1, l2, h2, l3, h3;
                unpack2(u[e][0], l0, h0); unpack2(u[e][1], l1, h1);
                unpack2(u[e][2], l2, h2); unpack2(u[e][3], l3, h3);
                mv[e][0] = siluf(l0 + h0 + b2.x);
                mv[e][1] = siluf(l1 + h1 + b2.y);
                mv[e][2] = siluf(l2 + h2 + b2.z);
                mv[e][3] = siluf(l3 + h3 + b2.w);
                part[e] = mv[e][0]*aw4.x + mv[e][1]*aw4.y + mv[e][2]*aw4.z + mv[e][3]*aw4.w;
            }
#pragma unroll
            for (int off = 1; off < 16; off <<= 1)
#pragma unroll
                for (int e = 0; e < 6; ++e)
                    part[e] += __shfl_xor_sync(0xffffffffu, part[e], off);
#pragma unroll
            for (int e = 0; e < 6; ++e) {
                const int eg  = p * 12 + hw * 6 + e;
                const int mol = (eg >= 21) ? 1 : 0;
                const int pad = (eg - mol * 21 >= PN - 1);
                const float gate = sigmf_(part[e] + abv);
                mv[e][0] *= gate; mv[e][1] *= gate; mv[e][2] *= gate; mv[e][3] *= gate;
                if (!pad) {
                    if (mol == 0) { agA0 += mv[e][0]; agA1 += mv[e][1];
                                    agA2 += mv[e][2]; agA3 += mv[e][3]; }
                    else          { agB0 += mv[e][0]; agB1 += mv[e][1];
                                    agB2 += mv[e][2]; agB3 += mv[e][3]; }
                }
            }
            __syncwarp();   /* gemv2 reads of t1 complete */
#pragma unroll
            for (int e = 0; e < 6; ++e) {
                float4 o; o.x = mv[e][0]; o.y = mv[e][1]; o.z = mv[e][2]; o.w = mv[e][3];
                *(float4*)&actm[e * HN + c4] = o;
            }
            __syncwarp();

            /* GEMV3: c1 = silu(m @ cw1 + cb1); scal = tanh(c1 @ cw2)*CR */
            ull q[6][4];
#pragma unroll
            for (int e = 0; e < 6; ++e) {
                q[e][0] = 0ull; q[e][1] = 0ull; q[e][2] = 0ull; q[e][3] = 0ull;
            }
            gemvKP6(&sm[OFF_CW1], actm, c4, xorv, q);

            const float4 cb  = *(const float4*)&sm[OFF_CB1 + c4];
            const float4 cw4 = *(const float4*)&sm[OFF_CW2 + c4];
            float s[6];
#pragma unroll
            for (int e = 0; e < 6; ++e) {
                float l0, h0, l1, h1, l2, h2, l3, h3;
                unpack2(q[e][0], l0, h0); unpack2(q[e][1], l1, h1);
                unpack2(q[e][2], l2, h2); unpack2(q[e][3], l3, h3);
                s[e] = siluf(l0 + h0 + cb.x) * cw4.x + siluf(l1 + h1 + cb.y) * cw4.y
                     + siluf(l2 + h2 + cb.z) * cw4.z + siluf(l3 + h3 + cb.w) * cw4.w;
            }
#pragma unroll
            for (int off = 1; off < 16; off <<= 1)
#pragma unroll
                for (int e = 0; e < 6; ++e)
                    s[e] += __shfl_xor_sync(0xffffffffu, s[e], off);
#pragma unroll
            for (int e = 0; e < 6; ++e) {
                const int eg  = p * 12 + hw * 6 + e;
                const int mol = (eg >= 21) ? 1 : 0;
                const int r   = eg - mol * 21;
                const int pad = (r >= PN - 1);
                int j = (r < i) ? r : r + 1;
                if (pad) j = i;
                const int mo68 = mol * 68;
                const float dx = sm[OFF_CRD + mo68 + i*3+0] - sm[OFF_CRD + mo68 + j*3+0];
                const float dy = sm[OFF_CRD + mo68 + i*3+1] - sm[OFF_CRD + mo68 + j*3+1];
                const float dz = sm[OFF_CRD + mo68 + i*3+2] - sm[OFF_CRD + mo68 + j*3+2];
                const float radial = dx*dx + dy*dy + dz*dz;
                const float inv = 1.f / (sqrtf(radial) + 1.f);
                const float scal = tanhfast(s[e]) * CRC * inv;
                if (mol == 0) { dcA0 += dx*scal; dcA1 += dy*scal; dcA2 += dz*scal; }
                else          { dcB0 += dx*scal; dcB1 += dy*scal; dcB2 += dz*scal; }
            }
            __syncwarp();   /* gemv3 reads done before next pass rewrites actm */
        }

        /* combine half-warps (disjoint edge sets) */
        dcA0 += __shfl_xor_sync(0xffffffffu, dcA0, 16);
        dcA1 += __shfl_xor_sync(0xffffffffu, dcA1, 16);
        dcA2 += __shfl_xor_sync(0xffffffffu, dcA2, 16);
        dcB0 += __shfl_xor_sync(0xffffffffu, dcB0, 16);
        dcB1 += __shfl_xor_sync(0xffffffffu, dcB1, 16);
        dcB2 += __shfl_xor_sync(0xffffffffu, dcB2, 16);
        agA0 += __shfl_xor_sync(0xffffffffu, agA0, 16);
        agA1 += __shfl_xor_sync(0xffffffffu, agA1, 16);
        agA2 += __shfl_xor_sync(0xffffffffu, agA2, 16);
        agA3 += __shfl_xor_sync(0xffffffffu, agA3, 16);
        agB0 += __shfl_xor_sync(0xffffffffu, agB0, 16);
        agB1 += __shfl_xor_sync(0xffffffffu, agB1, 16);
        agB2 += __shfl_xor_sync(0xffffffffu, agB2, 16);
        agB3 += __shfl_xor_sync(0xffffffffu, agB3, 16);
        if (hw == 0) {
            float4 a0; a0.x = agA0; a0.y = agA1; a0.z = agA2; a0.w = agA3;
            float4 b0v; b0v.x = agB0; b0v.y = agB1; b0v.z = agB2; b0v.w = agB3;
            *(float4*)&aggp[c4] = a0;
            *(float4*)&aggp[64 + c4] = b0v;
        }
        __syncthreads();   /* all phase-2 reads of CRD/HR/HC done; agg staged */

        /* ---- phase 3: coord update + node MLP for node i, both molecules ---- */
#pragma unroll
        for (int m = 0; m < 2; ++m) {
            if (lane == 0) {
                sm[OFF_CRD + m * 68 + i * 3 + 0] += m ? dcB0 : dcA0;
                sm[OFF_CRD + m * 68 + i * 3 + 1] += m ? dcB1 : dcA1;
                sm[OFF_CRD + m * 68 + i * 3 + 2] += m ? dcB2 : dcA2;
            }
            ull g2 = *(const ull*)&sm[OFF_NB1 + 2 * lane];
#pragma unroll 8
            for (int k = 0; k < HN; ++k) {
                const float a = sm[OFF_H + m * 1408 + i * 64 + k];
                ffma2(g2, pack2(a, a), *(const ull*)&sm[OFF_NW1 + k * HN + 2 * lane]);
            }
#pragma unroll 8
            for (int k = 0; k < HN; ++k) {
                const float a = aggp[m * 64 + k];
                ffma2(g2, pack2(a, a), *(const ull*)&sm[OFF_NW1 + (HN + k) * HN + 2 * lane]);
            }
            float g0, g1; unpack2(g2, g0, g1);
            g0 = siluf(g0); g1 = siluf(g1);
            wbf[2 * lane] = g0; wbf[2 * lane + 1] = g1;
            __syncwarp();
            ull o2 = *(const ull*)&sm[OFF_NB2 + 2 * lane];
#pragma unroll 8
            for (int k = 0; k < HN; ++k) {
                const float a = wbf[k];
                ffma2(o2, pack2(a, a), *(const ull*)&sm[OFF_NW2 + k * HN + 2 * lane]);
            }
            float o0, o1; unpack2(o2, o0, o1);
            __syncwarp();   /* wbf reads complete before m=1 overwrites */
            sm[OFF_H + m * 1408 + i * 64 + 2 * lane]     += o0;
            sm[OFF_H + m * 1408 + i * 64 + 2 * lane + 1] += o1;
        }
        __syncthreads();
    } /* layer loop */

    /* ---- velocity + mean removal (both molecules) ---- */
    for (int idx = tid; idx < 2 * PN * DN; idx += NTHREADS) {
        const int m = idx / 66, rem = idx - m * 66;
        sm[OFF_VEL + m * 68 + rem] = sm[OFF_CRD + m * 68 + rem] - sm[OFF_CR0 + m * 68 + rem];
    }
    __syncthreads();
    if (tid < 6) {
        const int m = tid / 3, d = tid - m * 3;
        float s = 0.f;
        for (int k = 0; k < PN; ++k) s += sm[OFF_VEL + m * 68 + k * 3 + d];
        sm[OFF_MEAN + m * 4 + d] = s * (1.f / PN);
    }
    __syncthreads();
    for (int idx = tid; idx < 2 * PN * DN; idx += NTHREADS) {
        const int m = idx / 66, rem = idx - m * 66;
        out[(b0 + m) * 66 + rem] = sm[OFF_VEL + m * 68 + rem] - sm[OFF_MEAN + m * 4 + rem % 3];
    }
}

extern "C" void kernel_launch(void* const* d_in, const int* in_sizes, int n_in,
                              void* d_out, int out_size)
{
    const float* t    = (const float*)d_in[0];
    const float* x    = (const float*)d_in[1];
    const float* embW = (const float*)d_in[2];
    const float* embb = (const float*)d_in[3];
    /* d_in[4] out_W, d_in[5] out_b: dead code (output depends only on coords) */
    const float* ew1  = (const float*)d_in[6];
    const float* eb1  = (const float*)d_in[7];
    const float* ew2  = (const float*)d_in[8];
    const float* eb2  = (const float*)d_in[9];
    const float* nw1  = (const float*)d_in[10];
    const float* nb1  = (const float*)d_in[11];
    const float* nw2  = (const float*)d_in[12];
    const float* nb2  = (const float*)d_in[13];
    const float* cw1  = (const float*)d_in[14];
    const float* cb1  = (const float*)d_in[15];
    const float* cw2  = (const float*)d_in[16];
    const float* aw   = (const float*)d_in[17];
    const float* ab   = (const float*)d_in[18];
    /* d_in[19] rows, d_in[20] cols: structure known analytically */

    const int B = in_sizes[0];
    const size_t smem = (size_t)SMEM_FLOATS * sizeof(float);
    cudaFuncSetAttribute(egnn_kernel, cudaFuncAttributeMaxDynamicSharedMemorySize, (int)smem);
    egnn_kernel<<<B / 2, NTHREADS, smem>>>(t, x, embW, embb, ew1, eb1, ew2, eb2,
                                           nw1, nb1, nw2, nb2, cw1, cb1, cw2, aw, ab,
                                           (float*)d_out);
}

// round 13
// speedup vs baseline: 1.0802x; 1.0802x over previous
#include <cuda_runtime.h>
#include <math.h>

#define PN 22
#define DN 3
#define HN 64
#define LN 5
#define NWARP 22
#define NTHREADS 704
#define CRC 3.0f       /* 15.0 / 5 layers */
#define LOG2M 7.0f

typedef unsigned long long ull;

/* ---- shared memory layout (floats) ---- */
constexpr int OFF_EW2  = 0;        /* 64*64  col-major + k-swizzle */
constexpr int OFF_CW1  = 4096;     /* 64*64  col-major + k-swizzle */
constexpr int OFF_NW1  = 8192;     /* 128*64 row-major */
constexpr int OFF_NW2  = 16384;    /* 64*64  row-major */
constexpr int OFF_EW1R = 20480;    /* ew1 rows 128,129 -> 128 floats */
constexpr int OFF_EB1  = 20608;
constexpr int OFF_EB2  = 20672;
constexpr int OFF_NB1  = 20736;
constexpr int OFF_NB2  = 20800;
constexpr int OFF_CB1  = 20864;
constexpr int OFF_CW2  = 20928;
constexpr int OFF_AW   = 20992;
constexpr int OFF_AB   = 21056;    /* +pad */
constexpr int OFF_H    = 21060;    /* 2 * 22*64 */
constexpr int OFF_HR   = 23876;
constexpr int OFF_HC   = 26692;
constexpr int OFF_EA   = 29508;    /* 2 * 484 */
constexpr int OFF_CRD  = 30476;    /* 2 * 68 */
constexpr int OFF_CR0  = 30612;
constexpr int OFF_VEL  = 30748;
constexpr int OFF_MEAN = 30884;    /* 8 */
constexpr int OFF_AGG  = 30892;    /* 22 warps * 2 mols * 64 = 2816 */
constexpr int OFF_WB   = 33708;    /* 22 warps * 8 edges * 64 = 11264 floats */
constexpr int SMEM_FLOATS = 44972; /* 179,888 bytes */

__device__ __forceinline__ float sigmf_(float v) {
    return __fdividef(1.f, 1.f + __expf(-v));
}
__device__ __forceinline__ float siluf(float v) { return v * sigmf_(v); }
__device__ __forceinline__ float tanhfast(float v) {
    const float e2 = __expf(2.f * v);
    return 1.f - __fdividef(2.f, e2 + 1.f);
}

__device__ __forceinline__ void ffma2(ull& d, ull a, ull b) {
    asm("fma.rn.f32x2 %0, %1, %2, %0;" : "+l"(d) : "l"(a), "l"(b));
}
__device__ __forceinline__ ull pack2(float x, float y) {
    ull r; asm("mov.b64 %0, {%1, %2};" : "=l"(r) : "f"(x), "f"(y)); return r;
}
__device__ __forceinline__ void unpack2(ull v, float& x, float& y) {
    asm("mov.b64 {%0, %1}, %2;" : "=f"(x), "=f"(y) : "l"(v));
}

/* k-paired 8-edge GEMV (4 per half-warp), 4 cols/lane, zero packs.
   WmT: 64x64 col-major, swizzled: W[k][c] stored at WmT[c*64 + (k ^ swz(c))],
   swz(c) = ((c>>2)&7)<<2.  Lane handling cols c4..c4+3 reads weights at
   kx = k ^ xorv (xorv == swz(c4), constant per lane) -> after the double-XOR
   the register pair is {W[k][c],W[k+1][c]}.  Activations stored plain, read
   at plain k (broadcast).  u[e][q] accumulates col c4+q (lo=even k, hi=odd). */
__device__ __forceinline__ void gemvKP4(const float* __restrict__ WmT,
                                        const float* __restrict__ actf,
                                        const int c4, const int xorv, ull u[4][4])
{
#pragma unroll 4
    for (int k = 0; k < HN; k += 4) {
        const int kx = k ^ xorv;
        const ulonglong2 w0 = *(const ulonglong2*)&WmT[(c4 + 0) * HN + kx];
        const ulonglong2 w1 = *(const ulonglong2*)&WmT[(c4 + 1) * HN + kx];
        const ulonglong2 w2 = *(const ulonglong2*)&WmT[(c4 + 2) * HN + kx];
        const ulonglong2 w3 = *(const ulonglong2*)&WmT[(c4 + 3) * HN + kx];
#pragma unroll
        for (int e = 0; e < 4; ++e) {
            const ulonglong2 a = *(const ulonglong2*)&actf[e * HN + k];
            ffma2(u[e][0], a.x, w0.x); ffma2(u[e][0], a.y, w0.y);
            ffma2(u[e][1], a.x, w1.x); ffma2(u[e][1], a.y, w1.y);
            ffma2(u[e][2], a.x, w2.x); ffma2(u[e][2], a.y, w2.y);
            ffma2(u[e][3], a.x, w3.x); ffma2(u[e][3], a.y, w3.y);
        }
    }
}

__global__ __launch_bounds__(NTHREADS, 1)
void egnn_kernel(const float* __restrict__ t, const float* __restrict__ x,
                 const float* __restrict__ embW, const float* __restrict__ embb,
                 const float* __restrict__ ew1, const float* __restrict__ eb1,
                 const float* __restrict__ ew2, const float* __restrict__ eb2,
                 const float* __restrict__ nw1, const float* __restrict__ nb1,
                 const float* __restrict__ nw2, const float* __restrict__ nb2,
                 const float* __restrict__ cw1, const float* __restrict__ cb1,
                 const float* __restrict__ cw2, const float* __restrict__ aw,
                 const float* __restrict__ ab, float* __restrict__ out)
{
    extern __shared__ float sm[];
    const int tid = threadIdx.x;
    const int b0 = blockIdx.x * 2;       /* molecules b0, b0+1 */
    const int w = tid >> 5;
    const int lane = tid & 31;
    const int hw = lane >> 4;            /* half-warp: edge subset */
    const int c4 = (lane & 15) * 4;      /* 4 output cols per lane */
    const int xorv = (lane & 7) << 2;    /* == swz(c4) */
    const int i = w;                     /* node owned by this warp (both mols) */

    /* ---- init: coords, h, edge_attr ---- */
    for (int idx = tid; idx < 2 * PN * DN; idx += NTHREADS) {
        const int m = idx / 66, rem = idx - m * 66;
        const float c = x[(b0 + m) * 66 + rem];
        sm[OFF_CRD + m * 68 + rem] = c;
        sm[OFF_CR0 + m * 68 + rem] = c;
    }
    const float tA = t[b0], tB = t[b0 + 1];
    for (int idx = tid; idx < 2 * PN * HN; idx += NTHREADS) {
        const int m = idx / 1408, q = idx - m * 1408;
        const int ii = q >> 6, o = q & 63;
        const float tb = m ? tB : tA;
        sm[OFF_H + m * 1408 + q] = embW[ii * HN + o] + tb * embW[22 * HN + o]
                                 + LOG2M * embW[23 * HN + o] + embb[o];
    }
    __syncthreads();
    for (int idx = tid; idx < 2 * PN * PN; idx += NTHREADS) {
        const int m = idx / 484, q = idx - m * 484;
        const int ii = q / PN, jj = q - ii * PN;
        const float dx = sm[OFF_CRD + m*68 + ii*3+0] - sm[OFF_CRD + m*68 + jj*3+0];
        const float dy = sm[OFF_CRD + m*68 + ii*3+1] - sm[OFF_CRD + m*68 + jj*3+1];
        const float dz = sm[OFF_CRD + m*68 + ii*3+2] - sm[OFF_CRD + m*68 + jj*3+2];
        sm[OFF_EA + m*484 + q] = dx*dx + dy*dy + dz*dz;
    }
    /* ordered before use by the weight-staging barrier below */

    float* const actm = sm + OFF_WB + w * 512 + hw * 256;  /* my half: 4x64 */
    float* const wbf  = sm + OFF_WB + w * 512;             /* warp scratch (phase 3) */
    float* const aggp = sm + OFF_AGG + w * 128;            /* [mol][64], dedicated */

    for (int l = 0; l < LN; ++l) {
        const float* s1 = ew1 + l * 8320;    /* rows 0..127 read straight from L2 */
        /* ---- stage this layer's weights (ew2/cw1 transposed + swizzled) ---- */
        {
            const float* s2 = ew2 + l * 4096;
            for (int q0 = tid; q0 < 4096; q0 += NTHREADS) {
                const int k = q0 >> 6, c = q0 & 63;
                sm[OFF_EW2 + c * 64 + (k ^ (((c >> 2) & 7) << 2))] = s2[q0];
            }
            const float* s5 = cw1 + l * 4096;
            for (int q0 = tid; q0 < 4096; q0 += NTHREADS) {
                const int k = q0 >> 6, c = q0 & 63;
                sm[OFF_CW1 + c * 64 + (k ^ (((c >> 2) & 7) << 2))] = s5[q0];
            }
            const float* s3 = nw1 + l * 8192;
            for (int q0 = tid; q0 < 8192; q0 += NTHREADS) sm[OFF_NW1 + q0] = s3[q0];
            const float* s4 = nw2 + l * 4096;
            for (int q0 = tid; q0 < 4096; q0 += NTHREADS) sm[OFF_NW2 + q0] = s4[q0];
            if (tid < 128) sm[OFF_EW1R + tid] = s1[128 * 64 + tid];
            if (tid >= 128 && tid < 192) {
                const int o = tid - 128;
                sm[OFF_EB1 + o] = eb1[l * 64 + o];
                sm[OFF_EB2 + o] = eb2[l * 64 + o];
                sm[OFF_NB1 + o] = nb1[l * 64 + o];
                sm[OFF_NB2 + o] = nb2[l * 64 + o];
                sm[OFF_CB1 + o] = cb1[l * 64 + o];
                sm[OFF_CW2 + o] = cw2[l * 64 + o];
                sm[OFF_AW + o]  = aw[l * 64 + o];
            }
            if (tid == 0) sm[OFF_AB] = ab[l];
        }
        __syncthreads();

        /* ---- phase 1: Hr/Hc for node i, both molecules (ew1 via L2) ---- */
        {
            ull r2a = 0ull, c2a = 0ull, r2b = 0ull, c2b = 0ull;
            const float* hA = &sm[OFF_H + i * 64];
            const float* hB = &sm[OFF_H + 1408 + i * 64];
#pragma unroll 4
            for (int k = 0; k < HN; ++k) {
                const ull wr = *(const ull*)&s1[k * 64 + 2 * lane];
                const ull wc = *(const ull*)&s1[(64 + k) * 64 + 2 * lane];
                const float aA = hA[k]; const ull apA = pack2(aA, aA);
                const float aB = hB[k]; const ull apB = pack2(aB, aB);
                ffma2(r2a, apA, wr); ffma2(c2a, apA, wc);
                ffma2(r2b, apB, wr); ffma2(c2b, apB, wc);
            }
            *(ull*)&sm[OFF_HR + i * 64 + 2 * lane] = r2a;
            *(ull*)&sm[OFF_HC + i * 64 + 2 * lane] = c2a;
            *(ull*)&sm[OFF_HR + 1408 + i * 64 + 2 * lane] = r2b;
            *(ull*)&sm[OFF_HC + 1408 + i * 64 + 2 * lane] = c2b;
        }
        __syncthreads();

        /* ---- phase 2: 48-slot edge stream (2 mols x 21 + 6 pad),
                8 edges per pass (4 per half-warp), 6 passes ---- */
        float dcA0 = 0.f, dcA1 = 0.f, dcA2 = 0.f;
        float dcB0 = 0.f, dcB1 = 0.f, dcB2 = 0.f;
        float agA0 = 0.f, agA1 = 0.f, agA2 = 0.f, agA3 = 0.f;
        float agB0 = 0.f, agB1 = 0.f, agB2 = 0.f, agB3 = 0.f;

#pragma unroll 1
        for (int p = 0; p < 6; ++p) {
            /* setup: t1 = silu(e_in @ ew1 + eb1) -> actm (plain floats) */
            {
                const float4 w128 = *(const float4*)&sm[OFF_EW1R + c4];
                const float4 w129 = *(const float4*)&sm[OFF_EW1R + 64 + c4];
                const float4 b1   = *(const float4*)&sm[OFF_EB1 + c4];
#pragma unroll
                for (int e = 0; e < 4; ++e) {
                    const int eg  = p * 8 + hw * 4 + e;
                    const int mol = (eg >= 21) ? 1 : 0;
                    const int r   = eg - mol * 21;
                    const int pad = (r >= PN - 1);
                    int j = (r < i) ? r : r + 1;
                    if (pad) j = i;
                    const int mo68 = mol * 68, mo14 = mol * 1408, mo484 = mol * 484;
                    const float dx = sm[OFF_CRD + mo68 + i*3+0] - sm[OFF_CRD + mo68 + j*3+0];
                    const float dy = sm[OFF_CRD + mo68 + i*3+1] - sm[OFF_CRD + mo68 + j*3+1];
                    const float dz = sm[OFF_CRD + mo68 + i*3+2] - sm[OFF_CRD + mo68 + j*3+2];
                    const float radial = dx*dx + dy*dy + dz*dz;
                    const float eav = sm[OFF_EA + mo484 + i * PN + j];
                    const float4 hr = *(const float4*)&sm[OFF_HR + mo14 + i * 64 + c4];
                    const float4 hc = *(const float4*)&sm[OFF_HC + mo14 + j * 64 + c4];
                    float4 o;
                    o.x = siluf(hr.x + hc.x + b1.x + radial * w128.x + eav * w129.x);
                    o.y = siluf(hr.y + hc.y + b1.y + radial * w128.y + eav * w129.y);
                    o.z = siluf(hr.z + hc.z + b1.z + radial * w128.z + eav * w129.z);
                    o.w = siluf(hr.w + hc.w + b1.w + radial * w128.w + eav * w129.w);
                    *(float4*)&actm[e * HN + c4] = o;
                }
            }
            __syncwarp();

            /* GEMV2: m = silu(t1 @ ew2 + eb2) (k-paired, bias at epilogue) */
            ull u[4][4];
#pragma unroll
            for (int e = 0; e < 4; ++e) {
                u[e][0] = 0ull; u[e][1] = 0ull; u[e][2] = 0ull; u[e][3] = 0ull;
            }
            gemvKP4(&sm[OFF_EW2], actm, c4, xorv, u);

            const float4 b2  = *(const float4*)&sm[OFF_EB2 + c4];
            const float4 aw4 = *(const float4*)&sm[OFF_AW + c4];
            const float abv  = sm[OFF_AB];
            float mv[4][4], part[4];
#pragma unroll
            for (int e = 0; e < 4; ++e) {
                float l0, h0, l1, h1, l2, h2, l3, h3;
                unpack2(u[e][0], l0, h0); unpack2(u[e][1], l1, h1);
                unpack2(u[e][2], l2, h2); unpack2(u[e][3], l3, h3);
                mv[e][0] = siluf(l0 + h0 + b2.x);
                mv[e][1] = siluf(l1 + h1 + b2.y);
                mv[e][2] = siluf(l2 + h2 + b2.z);
                mv[e][3] = siluf(l3 + h3 + b2.w);
                part[e] = mv[e][0]*aw4.x + mv[e][1]*aw4.y + mv[e][2]*aw4.z + mv[e][3]*aw4.w;
            }
#pragma unroll
            for (int off = 1; off < 16; off <<= 1)
#pragma unroll
                for (int e = 0; e < 4; ++e)
                    part[e] += __shfl_xor_sync(0xffffffffu, part[e], off);
#pragma unroll
            for (int e = 0; e < 4; ++e) {
                const int eg  = p * 8 + hw * 4 + e;
                const int mol = (eg >= 21) ? 1 : 0;
                const int pad = (eg - mol * 21 >= PN - 1);
                const float gate = sigmf_(part[e] + abv);
                mv[e][0] *= gate; mv[e][1] *= gate; mv[e][2] *= gate; mv[e][3] *= gate;
                if (!pad) {
                    if (mol == 0) { agA0 += mv[e][0]; agA1 += mv[e][1];
                                    agA2 += mv[e][2]; agA3 += mv[e][3]; }
                    else          { agB0 += mv[e][0]; agB1 += mv[e][1];
                                    agB2 += mv[e][2]; agB3 += mv[e][3]; }
                }
            }
            __syncwarp();   /* gemv2 reads of t1 complete */
#pragma unroll
            for (int e = 0; e < 4; ++e) {
                float4 o; o.x = mv[e][0]; o.y = mv[e][1]; o.z = mv[e][2]; o.w = mv[e][3];
                *(float4*)&actm[e * HN + c4] = o;
            }
            __syncwarp();

            /* GEMV3: c1 = silu(m @ cw1 + cb1); scal = tanh(c1 @ cw2)*CR */
            ull q[4][4];
#pragma unroll
            for (int e = 0; e < 4; ++e) {
                q[e][0] = 0ull; q[e][1] = 0ull; q[e][2] = 0ull; q[e][3] = 0ull;
            }
            gemvKP4(&sm[OFF_CW1], actm, c4, xorv, q);

            const float4 cb  = *(const float4*)&sm[OFF_CB1 + c4];
            const float4 cw4 = *(const float4*)&sm[OFF_CW2 + c4];
            float s[4];
#pragma unroll
            for (int e = 0; e < 4; ++e) {
                float l0, h0, l1, h1, l2, h2, l3, h3;
                unpack2(q[e][0], l0, h0); unpack2(q[e][1], l1, h1);
                unpack2(q[e][2], l2, h2); unpack2(q[e][3], l3, h3);
                s[e] = siluf(l0 + h0 + cb.x) * cw4.x + siluf(l1 + h1 + cb.y) * cw4.y
                     + siluf(l2 + h2 + cb.z) * cw4.z + siluf(l3 + h3 + cb.w) * cw4.w;
            }
#pragma unroll
            for (int off = 1; off < 16; off <<= 1)
#pragma unroll
                for (int e = 0; e < 4; ++e)
                    s[e] += __shfl_xor_sync(0xffffffffu, s[e], off);
#pragma unroll
            for (int e = 0; e < 4; ++e) {
                const int eg  = p * 8 + hw * 4 + e;
                const int mol = (eg >= 21) ? 1 : 0;
                const int r   = eg - mol * 21;
                const int pad = (r >= PN - 1);
                int j = (r < i) ? r : r + 1;
                if (pad) j = i;
                const int mo68 = mol * 68;
                const float dx = sm[OFF_CRD + mo68 + i*3+0] - sm[OFF_CRD + mo68 + j*3+0];
                const float dy = sm[OFF_CRD + mo68 + i*3+1] - sm[OFF_CRD + mo68 + j*3+1];
                const float dz = sm[OFF_CRD + mo68 + i*3+2] - sm[OFF_CRD + mo68 + j*3+2];
                const float radial = dx*dx + dy*dy + dz*dz;
                const float inv = 1.f / (sqrtf(radial) + 1.f);
                const float scal = tanhfast(s[e]) * CRC * inv;
                if (mol == 0) { dcA0 += dx*scal; dcA1 += dy*scal; dcA2 += dz*scal; }
                else          { dcB0 += dx*scal; dcB1 += dy*scal; dcB2 += dz*scal; }
            }
            __syncwarp();   /* gemv3 reads done before next pass rewrites actm */
        }

        /* combine half-warps (disjoint edge sets) */
        dcA0 += __shfl_xor_sync(0xffffffffu, dcA0, 16);
        dcA1 += __shfl_xor_sync(0xffffffffu, dcA1, 16);
        dcA2 += __shfl_xor_sync(0xffffffffu, dcA2, 16);
        dcB0 += __shfl_xor_sync(0xffffffffu, dcB0, 16);
        dcB1 += __shfl_xor_sync(0xffffffffu, dcB1, 16);
        dcB2 += __shfl_xor_sync(0xffffffffu, dcB2, 16);
        agA0 += __shfl_xor_sync(0xffffffffu, agA0, 16);
        agA1 += __shfl_xor_sync(0xffffffffu, agA1, 16);
        agA2 += __shfl_xor_sync(0xffffffffu, agA2, 16);
        agA3 += __shfl_xor_sync(0xffffffffu, agA3, 16);
        agB0 += __shfl_xor_sync(0xffffffffu, agB0, 16);
        agB1 += __shfl_xor_sync(0xffffffffu, agB1, 16);
        agB2 += __shfl_xor_sync(0xffffffffu, agB2, 16);
        agB3 += __shfl_xor_sync(0xffffffffu, agB3, 16);
        if (hw == 0) {
            float4 a0; a0.x = agA0; a0.y = agA1; a0.z = agA2; a0.w = agA3;
            float4 b0v; b0v.x = agB0; b0v.y = agB1; b0v.z = agB2; b0v.w = agB3;
            *(float4*)&aggp[c4] = a0;
            *(float4*)&aggp[64 + c4] = b0v;
        }
        __syncthreads();   /* all phase-2 reads of CRD/HR/HC done; agg staged */

        /* ---- phase 3: coord update + node MLP for node i, both molecules ---- */
#pragma unroll
        for (int m = 0; m < 2; ++m) {
            if (lane == 0) {
                sm[OFF_CRD + m * 68 + i * 3 + 0] += m ? dcB0 : dcA0;
                sm[OFF_CRD + m * 68 + i * 3 + 1] += m ? dcB1 : dcA1;
                sm[OFF_CRD + m * 68 + i * 3 + 2] += m ? dcB2 : dcA2;
            }
            ull g2 = *(const ull*)&sm[OFF_NB1 + 2 * lane];
#pragma unroll 8
            for (int k = 0; k < HN; ++k) {
                const float a = sm[OFF_H + m * 1408 + i * 64 + k];
                ffma2(g2, pack2(a, a), *(const ull*)&sm[OFF_NW1 + k * HN + 2 * lane]);
            }
#pragma unroll 8
            for (int k = 0; k < HN; ++k) {
                const float a = aggp[m * 64 + k];
                ffma2(g2, pack2(a, a), *(const ull*)&sm[OFF_NW1 + (HN + k) * HN + 2 * lane]);
            }
            float g0, g1; unpack2(g2, g0, g1);
            g0 = siluf(g0); g1 = siluf(g1);
            wbf[2 * lane] = g0; wbf[2 * lane + 1] = g1;
            __syncwarp();
            ull o2 = *(const ull*)&sm[OFF_NB2 + 2 * lane];
#pragma unroll 8
            for (int k = 0; k < HN; ++k) {
                const float a = wbf[k];
                ffma2(o2, pack2(a, a), *(const ull*)&sm[OFF_NW2 + k * HN + 2 * lane]);
            }
            float o0, o1; unpack2(o2, o0, o1);
            __syncwarp();   /* wbf reads complete before m=1 overwrites */
            sm[OFF_H + m * 1408 + i * 64 + 2 * lane]     += o0;
            sm[OFF_H + m * 1408 + i * 64 + 2 * lane + 1] += o1;
        }
        __syncthreads();
    } /* layer loop */

    /* ---- velocity + mean removal (both molecules) ---- */
    for (int idx = tid; idx < 2 * PN * DN; idx += NTHREADS) {
        const int m = idx / 66, rem = idx - m * 66;
        sm[OFF_VEL + m * 68 + rem] = sm[OFF_CRD + m * 68 + rem] - sm[OFF_CR0 + m * 68 + rem];
    }
    __syncthreads();
    if (tid < 6) {
        const int m = tid / 3, d = tid - m * 3;
        float s = 0.f;
        for (int k = 0; k < PN; ++k) s += sm[OFF_VEL + m * 68 + k * 3 + d];
        sm[OFF_MEAN + m * 4 + d] = s * (1.f / PN);
    }
    __syncthreads();
    for (int idx = tid; idx < 2 * PN * DN; idx += NTHREADS) {
        const int m = idx / 66, rem = idx - m * 66;
        out[(b0 + m) * 66 + rem] = sm[OFF_VEL + m * 68 + rem] - sm[OFF_MEAN + m * 4 + rem % 3];
    }
}

extern "C" void kernel_launch(void* const* d_in, const int* in_sizes, int n_in,
                              void* d_out, int out_size)
{
    const float* t    = (const float*)d_in[0];
    const float* x    = (const float*)d_in[1];
    const float* embW = (const float*)d_in[2];
    const float* embb = (const float*)d_in[3];
    /* d_in[4] out_W, d_in[5] out_b: dead code (output depends only on coords) */
    const float* ew1  = (const float*)d_in[6];
    const float* eb1  = (const float*)d_in[7];
    const float* ew2  = (const float*)d_in[8];
    const float* eb2  = (const float*)d_in[9];
    const float* nw1  = (const float*)d_in[10];
    const float* nb1  = (const float*)d_in[11];
    const float* nw2  = (const float*)d_in[12];
    const float* nb2  = (const float*)d_in[13];
    const float* cw1  = (const float*)d_in[14];
    const float* cb1  = (const float*)d_in[15];
    const float* cw2  = (const float*)d_in[16];
    const float* aw   = (const float*)d_in[17];
    const float* ab   = (const float*)d_in[18];
    /* d_in[19] rows, d_in[20] cols: structure known analytically */

    const int B = in_sizes[0];
    const size_t smem = (size_t)SMEM_FLOATS * sizeof(float);
    cudaFuncSetAttribute(egnn_kernel, cudaFuncAttributeMaxDynamicSharedMemorySize, (int)smem);
    egnn_kernel<<<B / 2, NTHREADS, smem>>>(t, x, embW, embb, ew1, eb1, ew2, eb2,
                                           nw1, nb1, nw2, nb2, cw1, cb1, cw2, aw, ab,
                                           (float*)d_out);
}